// round 5
// baseline (speedup 1.0000x reference)
#include <cuda_runtime.h>
#include <cuda_bf16.h>

// PointPillarsScatter gather v4:
//  - byte-packed per-cell counts (1 MB, L2-resident): one u32 load covers a thread's 4 cells
//  - thread = (4 consecutive cells) x (8 channels): 2M threads -> deep latency hiding,
//    occupied-cell feats loads fully unrolled/independent (high MLP)
//  - all output stores are full-warp STG.128 (__stcs), each line written exactly once
//
// Inputs:
//   d_in[0]: pillar_feats  float32 [B=4, P=30000, C=64]
//   d_in[1]: pillar_coords int32   [B=4, P=30000, 2]  (y, x)
// Output: float32 [4, 64, 512, 512]

#define BEV_H 512
#define BEV_W 512
#define HW (BEV_H * BEV_W)      // 262144 = 2^18
#define C_DIM 64
#define P_DIM 30000
#define B_DIM 4
#define CAP 8
#define NGRP ((B_DIM * HW) / 4) // 262144 cell groups (4 cells each)

__device__ unsigned int   d_count[NGRP];              // 1 MB: 4 x u8 counts per word
__device__ unsigned short d_list[B_DIM * HW * CAP];   // 16 MB

__global__ void pp_build_kernel(const int* __restrict__ coords) {
    int p = blockIdx.x * blockDim.x + threadIdx.x;
    if (p >= B_DIM * P_DIM) return;

    int2 yx = reinterpret_cast<const int2*>(coords)[p];
    int y = min(max(yx.x, 0), BEV_H - 1);
    int x = min(max(yx.y, 0), BEV_W - 1);

    int b   = p / P_DIM;
    int pid = p - b * P_DIM;
    int idx = b * HW + y * BEV_W + x;

    unsigned shift = (idx & 3) * 8;
    unsigned old = atomicAdd(&d_count[idx >> 2], 1u << shift);
    unsigned pos = (old >> shift) & 0xFFu;
    if (pos < CAP) d_list[(size_t)idx * CAP + pos] = (unsigned short)pid;
}

__global__ __launch_bounds__(256) void pp_gather_kernel(const float* __restrict__ feats,
                                                        float* __restrict__ out) {
    int tid = blockIdx.x * blockDim.x + threadIdx.x;  // 0 .. 8*NGRP
    int grp = tid & (NGRP - 1);     // cell group (consecutive across warp -> coalesced)
    int chg = tid >> 18;            // channel group 0..7 (8 channels each)

    int idx0  = grp << 2;           // first cell index (b*HW + cell)
    int b     = idx0 >> 18;
    int cell0 = idx0 & (HW - 1);

    unsigned cw = d_count[grp];     // 4 packed counts, L2 hit

    float acc[4][8];
    #pragma unroll
    for (int ci = 0; ci < 4; ci++)
        #pragma unroll
        for (int c = 0; c < 8; c++) acc[ci][c] = 0.0f;

    if (cw) {
        const float* fb = feats + (size_t)b * P_DIM * C_DIM + (chg << 3);
        #pragma unroll
        for (int ci = 0; ci < 4; ci++) {
            int n = (int)((cw >> (ci * 8)) & 0xFFu);
            if (n == 0) continue;
            n = min(n, CAP);
            // 16B pillar list for this cell
            uint4 lv = *reinterpret_cast<const uint4*>(&d_list[(size_t)(idx0 + ci) * CAP]);
            for (int i = 0; i < n; i++) {
                unsigned pid = lv.x & 0xFFFFu;
                // funnel-shift the 128-bit list right by 16
                lv.x = (lv.x >> 16) | (lv.y << 16);
                lv.y = (lv.y >> 16) | (lv.z << 16);
                lv.z = (lv.z >> 16) | (lv.w << 16);
                lv.w =  lv.w >> 16;

                const float4* fp = reinterpret_cast<const float4*>(fb + (size_t)pid * C_DIM);
                float4 v0 = fp[0], v1 = fp[1];
                acc[ci][0] += v0.x; acc[ci][1] += v0.y; acc[ci][2] += v0.z; acc[ci][3] += v0.w;
                acc[ci][4] += v1.x; acc[ci][5] += v1.y; acc[ci][6] += v1.z; acc[ci][7] += v1.w;
            }
        }
    }

    float* o = out + ((size_t)b * C_DIM + (size_t)(chg << 3)) * HW + cell0;
    #pragma unroll
    for (int c = 0; c < 8; c++) {
        float4 v = make_float4(acc[0][c], acc[1][c], acc[2][c], acc[3][c]);
        __stcs(reinterpret_cast<float4*>(o + (size_t)c * HW), v);
    }
}

extern "C" void kernel_launch(void* const* d_in, const int* in_sizes, int n_in,
                              void* d_out, int out_size) {
    const float* feats  = (const float*)d_in[0];
    const int*   coords = (const int*)d_in[1];
    float*       out    = (float*)d_out;

    // Zero the packed counters (1 MB, graph-capturable)
    void* count_ptr = nullptr;
    cudaGetSymbolAddress(&count_ptr, d_count);
    cudaMemsetAsync(count_ptr, 0, NGRP * sizeof(unsigned int));

    int n_pillars = B_DIM * P_DIM;                 // 120,000
    pp_build_kernel<<<(n_pillars + 255) / 256, 256>>>(coords);

    int n_threads = 8 * NGRP;                      // 2,097,152
    pp_gather_kernel<<<n_threads / 256, 256>>>(feats, out);
}

// round 6
// speedup vs baseline: 1.1080x; 1.1080x over previous
#include <cuda_runtime.h>
#include <cuda_bf16.h>

// PointPillarsScatter gather v5:
//  - byte-packed per-cell counts (1 MB, L2-resident): one u32 load covers a thread's 4 cells
//  - thread = (4 consecutive cells) x (4 channels): 16-reg accumulator file -> ~40 regs,
//    2x occupancy vs v4; 4.2M threads of wave depth
//  - pillar ids loaded as lazy u16 hits (no register-hungry uint4 funnel decode)
//  - all output stores are full-warp STG.128 (__stcs), each line written exactly once
//
// Inputs:
//   d_in[0]: pillar_feats  float32 [B=4, P=30000, C=64]
//   d_in[1]: pillar_coords int32   [B=4, P=30000, 2]  (y, x)
// Output: float32 [4, 64, 512, 512]

#define BEV_H 512
#define BEV_W 512
#define HW (BEV_H * BEV_W)      // 262144 = 2^18
#define C_DIM 64
#define P_DIM 30000
#define B_DIM 4
#define CAP 8
#define NGRP ((B_DIM * HW) / 4) // 262144 cell groups (4 cells each)

__device__ unsigned int   d_count[NGRP];              // 1 MB: 4 x u8 counts per word
__device__ unsigned short d_list[B_DIM * HW * CAP];   // 16 MB

__global__ void pp_build_kernel(const int* __restrict__ coords) {
    int p = blockIdx.x * blockDim.x + threadIdx.x;
    if (p >= B_DIM * P_DIM) return;

    int2 yx = reinterpret_cast<const int2*>(coords)[p];
    int y = min(max(yx.x, 0), BEV_H - 1);
    int x = min(max(yx.y, 0), BEV_W - 1);

    int b   = p / P_DIM;
    int pid = p - b * P_DIM;
    int idx = b * HW + y * BEV_W + x;

    unsigned shift = (idx & 3) * 8;
    unsigned old = atomicAdd(&d_count[idx >> 2], 1u << shift);
    unsigned pos = (old >> shift) & 0xFFu;
    if (pos < CAP) d_list[(size_t)idx * CAP + pos] = (unsigned short)pid;
}

__global__ __launch_bounds__(256) void pp_gather_kernel(const float* __restrict__ feats,
                                                        float* __restrict__ out) {
    int tid = blockIdx.x * blockDim.x + threadIdx.x;  // 0 .. 16*NGRP
    int grp = tid & (NGRP - 1);     // cell group (consecutive across warp -> coalesced)
    int chg = tid >> 18;            // channel group 0..15 (4 channels each)

    int idx0  = grp << 2;           // first cell index (b*HW + cell)
    int b     = idx0 >> 18;
    int cell0 = idx0 & (HW - 1);

    unsigned cw = d_count[grp];     // 4 packed counts, L2 hit

    float acc[4][4];
    #pragma unroll
    for (int ci = 0; ci < 4; ci++)
        #pragma unroll
        for (int c = 0; c < 4; c++) acc[ci][c] = 0.0f;

    if (cw) {
        const float* fb = feats + (size_t)b * P_DIM * C_DIM + (chg << 2);
        const unsigned short* lst = &d_list[(size_t)idx0 * CAP];
        #pragma unroll
        for (int ci = 0; ci < 4; ci++) {
            int n = (int)((cw >> (ci * 8)) & 0xFFu);
            n = min(n, CAP);
            for (int i = 0; i < n; i++) {
                unsigned pid = lst[ci * CAP + i];      // u16 L2/L1 hit
                float4 v = *reinterpret_cast<const float4*>(fb + (size_t)pid * C_DIM);
                acc[ci][0] += v.x; acc[ci][1] += v.y; acc[ci][2] += v.z; acc[ci][3] += v.w;
            }
        }
    }

    float* o = out + ((size_t)b * C_DIM + (size_t)(chg << 2)) * HW + cell0;
    #pragma unroll
    for (int c = 0; c < 4; c++) {
        float4 v = make_float4(acc[0][c], acc[1][c], acc[2][c], acc[3][c]);
        __stcs(reinterpret_cast<float4*>(o + (size_t)c * HW), v);
    }
}

extern "C" void kernel_launch(void* const* d_in, const int* in_sizes, int n_in,
                              void* d_out, int out_size) {
    const float* feats  = (const float*)d_in[0];
    const int*   coords = (const int*)d_in[1];
    float*       out    = (float*)d_out;

    // Zero the packed counters (1 MB, graph-capturable)
    void* count_ptr = nullptr;
    cudaGetSymbolAddress(&count_ptr, d_count);
    cudaMemsetAsync(count_ptr, 0, NGRP * sizeof(unsigned int));

    int n_pillars = B_DIM * P_DIM;                 // 120,000
    pp_build_kernel<<<(n_pillars + 255) / 256, 256>>>(coords);

    int n_threads = 16 * NGRP;                     // 4,194,304
    pp_gather_kernel<<<n_threads / 256, 256>>>(feats, out);
}